// round 16
// baseline (speedup 1.0000x reference)
#include <cuda_runtime.h>

// ---------------------------------------------------------------------------
// Fused SAN (pairwise) block, fp32 + packed f32x2 FMA (FFMA2), sm_103a.
// Two-kernel split:
//   K1: 80-ch 1x1 conv GEMM over all pixels -> global scratch (x1,x2,x3)
//   K2: per-tile halo staging from scratch + MLP + softmax + aggregation
// ---------------------------------------------------------------------------

#define IMG   256
#define PLANE (IMG*IMG)
#define NB    16

typedef unsigned long long u64;

__device__ float g_scr[NB * 80 * PLANE];   // 335.5 MB static scratch

__device__ __forceinline__ u64 pk2(float x, float y) {
    u64 r; asm("mov.b64 %0, {%1, %2};" : "=l"(r) : "f"(x), "f"(y)); return r;
}
__device__ __forceinline__ float2 up2(u64 v) {
    float2 f; asm("mov.b64 {%0, %1}, %2;" : "=f"(f.x), "=f"(f.y) : "l"(v)); return f;
}
__device__ __forceinline__ u64 ffma2(u64 a, u64 b, u64 c) {
    u64 d; asm("fma.rn.f32x2 %0, %1, %2, %3;" : "=l"(d) : "l"(a), "l"(b), "l"(c)); return d;
}
__device__ __forceinline__ int reflect(int i) {
    if (i < 0) return -i;
    if (i > IMG - 1) return 2 * (IMG - 1) - i;
    return i;
}

// ============================ K1: conv GEMM ================================
// 256 threads, 2 CTAs/SM. Each CTA: 128 pixels x 80 out-channels.
// smem: WD u64[64][80] dup-pairs (40KB) + BD u64[80] + XC[8][128] (4KB)

#define K1_THREADS 256
#define K1_PX      128          // pixels per CTA (64 pairs)
#define K1_WDF     0            // 10240 floats
#define K1_BDF     10240        // 160 floats
#define K1_XCF     10400        // 1024 floats
#define K1_SMEMF   11424
#define K1_SMEMB   (K1_SMEMF*4)

__global__ void __launch_bounds__(K1_THREADS, 2)
san_conv_kernel(const float* __restrict__ x,
                const float* __restrict__ c1w, const float* __restrict__ c1b,
                const float* __restrict__ c2w, const float* __restrict__ c2b,
                const float* __restrict__ c3w, const float* __restrict__ c3b)
{
    extern __shared__ float sm[];
    u64*   WD = (u64*)sm;                 // [64*80]
    u64*   BD = (u64*)(sm + K1_BDF);      // [80]
    float* XC = sm + K1_XCF;              // [8][128]
    const int tid = threadIdx.x;
    const int P0  = blockIdx.x * K1_PX;
    const int b   = blockIdx.y;

    // stage dup-pair weights + biases
    for (int i = tid; i < 64 * 80; i += K1_THREADS) {
        int c = i / 80, o = i - c * 80;
        float w = (o < 8) ? c1w[o * 64 + c] : (o < 16) ? c2w[(o - 8) * 64 + c]
                                                       : c3w[(o - 16) * 64 + c];
        WD[i] = pk2(w, w);
    }
    if (tid < 80) {
        float bb = (tid < 8) ? c1b[tid] : (tid < 16) ? c2b[tid - 8] : c3b[tid - 16];
        BD[tid] = pk2(bb, bb);
    }

    const float* xb = x + (size_t)b * 64 * PLANE + P0;
    const int hi = tid >> 7, px = tid & 127;

    float pf[4];
    #pragma unroll
    for (int k = 0; k < 4; k++)            // chunk 0 in flight
        pf[k] = xb[(size_t)(2 * k + hi) * PLANE + px];

    const int w    = tid >> 5;             // 0..7 = out-channel group
    const int lane = tid & 31;
    const int o0   = w * 10;
    const int pr0  = lane, pr1 = lane + 32;

    u64 acc[2][10];
    const u64* XC64 = (const u64*)XC;

    for (int cc = 0; cc < 8; cc++) {
        __syncthreads();                    // protect XC (and params on iter 0)
        #pragma unroll
        for (int k = 0; k < 4; k++)
            XC[(2 * k + hi) * 128 + px] = pf[k];
        __syncthreads();

        if (cc == 0) {
            #pragma unroll
            for (int o = 0; o < 10; o++) { acc[0][o] = BD[o0 + o]; acc[1][o] = acc[0][o]; }
        }
        if (cc < 7) {
            const float* src = xb + (size_t)(cc + 1) * 8 * PLANE;
            #pragma unroll
            for (int k = 0; k < 4; k++)
                pf[k] = src[(size_t)(2 * k + hi) * PLANE + px];
        }

        #pragma unroll
        for (int cl = 0; cl < 8; cl++) {
            const int c = cc * 8 + cl;
            const ulonglong2* wp = (const ulonglong2*)(WD + c * 80 + o0);
            ulonglong2 w01 = wp[0], w23 = wp[1], w45 = wp[2], w67 = wp[3], w89 = wp[4];
            u64 X0 = XC64[cl * 64 + pr0];
            u64 X1 = XC64[cl * 64 + pr1];
            acc[0][0] = ffma2(w01.x, X0, acc[0][0]); acc[1][0] = ffma2(w01.x, X1, acc[1][0]);
            acc[0][1] = ffma2(w01.y, X0, acc[0][1]); acc[1][1] = ffma2(w01.y, X1, acc[1][1]);
            acc[0][2] = ffma2(w23.x, X0, acc[0][2]); acc[1][2] = ffma2(w23.x, X1, acc[1][2]);
            acc[0][3] = ffma2(w23.y, X0, acc[0][3]); acc[1][3] = ffma2(w23.y, X1, acc[1][3]);
            acc[0][4] = ffma2(w45.x, X0, acc[0][4]); acc[1][4] = ffma2(w45.x, X1, acc[1][4]);
            acc[0][5] = ffma2(w45.y, X0, acc[0][5]); acc[1][5] = ffma2(w45.y, X1, acc[1][5]);
            acc[0][6] = ffma2(w67.x, X0, acc[0][6]); acc[1][6] = ffma2(w67.x, X1, acc[1][6]);
            acc[0][7] = ffma2(w67.y, X0, acc[0][7]); acc[1][7] = ffma2(w67.y, X1, acc[1][7]);
            acc[0][8] = ffma2(w89.x, X0, acc[0][8]); acc[1][8] = ffma2(w89.x, X1, acc[1][8]);
            acc[0][9] = ffma2(w89.y, X0, acc[0][9]); acc[1][9] = ffma2(w89.y, X1, acc[1][9]);
        }
    }

    float* scr = g_scr + (((size_t)b * 80 + o0) << 16) + P0;
    #pragma unroll
    for (int o = 0; o < 10; o++) {
        *(u64*)(scr + ((size_t)o << 16) + 2 * pr0) = acc[0][o];
        *(u64*)(scr + ((size_t)o << 16) + 2 * pr1) = acc[1][o];
    }
}

// ====================== K2: MLP + softmax + aggregation ====================
// 256 threads (1 thread = 1 pixel), 2 CTAs/SM. Tile 32x8, halo 34x10.

#define TILE_W 32
#define TILE_H 8
#define HW_    34
#define NHP    340
#define K2_THREADS 256

// smem float offsets
#define A1   0            // x1 interior [8][256]
#define A2   2048         // x2 halo     [8][340]
#define A3   4768         // x3 halo ch-pairs u64[32][340]  (21760 floats)
#define GX   26528        // gather idx  int[340]
#define T1o  26868        // folded bn1 shift [10]
#define WOo  26878        // folded w_out [8]
#define PWo  26886        // convp_w [4]
#define BOo  26890        // b_out [1]
#define T2o  26892        // folded bn2 shift pairs u64[4]
#define WMo  26900        // folded w_mid pairs u64[10][4]
#define K2_SMEMF 26980
#define K2_SMEMB (K2_SMEMF*4)   // 107,920 B

__global__ void __launch_bounds__(K2_THREADS, 2)
san_attn_kernel(const float* __restrict__ cpw,
                const float* __restrict__ bn1g, const float* __restrict__ bn1b,
                const float* __restrict__ bn1m, const float* __restrict__ bn1v,
                const float* __restrict__ wmid,
                const float* __restrict__ bn2g, const float* __restrict__ bn2b,
                const float* __restrict__ bn2m, const float* __restrict__ bn2v,
                const float* __restrict__ wout, const float* __restrict__ bout,
                float* __restrict__ out)
{
    extern __shared__ float sm[];
    const int tid = threadIdx.x;
    const int tx0 = blockIdx.x * TILE_W;
    const int ty0 = blockIdx.y * TILE_H;
    const int b   = blockIdx.z;

    // ---- params + gather table ----
    if (tid < 10) {
        float s1 = bn1g[tid] * rsqrtf(bn1v[tid] + 1e-5f);
        sm[T1o + tid] = (bn1b[tid] - bn1m[tid] * s1) / s1;
    }
    if (tid >= 32 && tid < 72) {            // w_mid o-pairs, pre-scaled by s1
        int i = tid - 32, c = i >> 2, op = i & 3;
        float s1c = bn1g[c] * rsqrtf(bn1v[c] + 1e-5f);
        ((u64*)(sm + WMo))[i] =
            pk2(wmid[(2 * op) * 10 + c] * s1c, wmid[(2 * op + 1) * 10 + c] * s1c);
    }
    if (tid >= 96 && tid < 100) {           // bn2 shift pairs
        int op = tid - 96;
        float tv[2];
        #pragma unroll
        for (int j = 0; j < 2; j++) {
            int o = 2 * op + j;
            float s2 = bn2g[o] * rsqrtf(bn2v[o] + 1e-5f);
            tv[j] = (bn2b[o] - bn2m[o] * s2) / s2;
        }
        ((u64*)(sm + T2o))[op] = pk2(tv[0], tv[1]);
    }
    if (tid >= 128 && tid < 136) {
        int o = tid - 128;
        float s2 = bn2g[o] * rsqrtf(bn2v[o] + 1e-5f);
        sm[WOo + o] = wout[o] * s2;
    }
    if (tid >= 160 && tid < 164) sm[PWo + tid - 160] = cpw[tid - 160];
    if (tid == 192) sm[BOo] = bout[0];
    for (int j = tid; j < NHP; j += K2_THREADS) {
        int hy = j / HW_, hx = j - hy * HW_;
        ((int*)sm)[GX + j] = reflect(ty0 - 1 + hy) * IMG + reflect(tx0 - 1 + hx);
    }
    __syncthreads();

    // ---- stage tiles from scratch ----
    const float* sb = g_scr + ((size_t)b * 80 << 16);
    const int* gix = (const int*)sm + GX;
    const int g1 = gix[tid];
    const int g2 = (tid < NHP - K2_THREADS) ? gix[tid + K2_THREADS] : 0;

    {   // x1 interior
        const int iy = tid >> 5, ix = tid & 31;
        const int gp = (ty0 + iy) * IMG + tx0 + ix;
        #pragma unroll
        for (int c = 0; c < 8; c++)
            sm[A1 + c * 256 + tid] = sb[((size_t)c << 16) + gp];
    }
    #pragma unroll
    for (int c = 0; c < 8; c++) {           // x2 halo
        const float* s2p = sb + ((size_t)(8 + c) << 16);
        float v0 = s2p[g1];
        float v1 = (tid < NHP - K2_THREADS) ? s2p[g2] : 0.0f;
        sm[A2 + c * NHP + tid] = v0;
        if (tid < NHP - K2_THREADS) sm[A2 + c * NHP + tid + K2_THREADS] = v1;
    }
    #pragma unroll 4
    for (int ch = 0; ch < 64; ch += 4) {    // x3 halo, channel-pair interleaved
        float v0[4], v1[4];
        #pragma unroll
        for (int q = 0; q < 4; q++) {
            const float* s3 = sb + ((size_t)(16 + ch + q) << 16);
            v0[q] = s3[g1];
            v1[q] = (tid < NHP - K2_THREADS) ? s3[g2] : 0.0f;
        }
        #pragma unroll
        for (int q = 0; q < 4; q++) {
            int cp = (ch + q) >> 1, lo = (ch + q) & 1;
            sm[A3 + (cp * NHP + tid) * 2 + lo] = v0[q];
            if (tid < NHP - K2_THREADS)
                sm[A3 + (cp * NHP + tid + K2_THREADS) * 2 + lo] = v1[q];
        }
    }
    __syncthreads();

    // ---- MLP -> softmax -> aggregation (1 thread = 1 pixel) ----
    const int iy = tid >> 5, ix = tid & 31;
    const int gx = tx0 + ix, gy = ty0 + iy;
    const int hs = (iy + 1) * HW_ + ix + 1;
    const float STEP = 2.0f / 255.0f;
    const float pw00 = sm[PWo], pw01 = sm[PWo + 1], pw10 = sm[PWo + 2], pw11 = sm[PWo + 3];
    const float t18 = sm[T1o + 8], t19 = sm[T1o + 9];
    const float boR = sm[BOo];

    float x1t[8];
    #pragma unroll
    for (int c = 0; c < 8; c++) x1t[c] = sm[A1 + c * 256 + tid] + sm[T1o + c];

    u64 t2p[4], wm8[4], wm9[4];
    #pragma unroll
    for (int op = 0; op < 4; op++) {
        t2p[op] = ((const u64*)(sm + T2o))[op];
        wm8[op] = ((const u64*)(sm + WMo))[8 * 4 + op];
        wm9[op] = ((const u64*)(sm + WMo))[9 * 4 + op];
    }
    float woR[8];
    #pragma unroll
    for (int o = 0; o < 8; o++) woR[o] = sm[WOo + o];

    float logits[9];
    #pragma unroll
    for (int k = 0; k < 9; k++) {
        const int dy = k / 3 - 1, dx = k - (k / 3) * 3 - 1;
        const int hn = hs + dy * HW_ + dx;
        float dlw = (float)(gx - reflect(gx + dx)) * STEP;
        float dlh = (float)(gy - reflect(gy + dy)) * STEP;
        float a8 = fmaxf(pw00 * dlw + pw01 * dlh + t18, 0.0f);
        float a9 = fmaxf(pw10 * dlw + pw11 * dlh + t19, 0.0f);
        u64 a8p = pk2(a8, a8), a9p = pk2(a9, a9);
        u64 h1p[4];
        #pragma unroll
        for (int op = 0; op < 4; op++)
            h1p[op] = ffma2(wm8[op], a8p, ffma2(wm9[op], a9p, t2p[op]));
        #pragma unroll
        for (int c = 0; c < 8; c++) {
            float a = fmaxf(x1t[c] - sm[A2 + c * NHP + hn], 0.0f);
            u64 ap = pk2(a, a);
            #pragma unroll
            for (int op = 0; op < 4; op++)
                h1p[op] = ffma2(((const u64*)(sm + WMo))[c * 4 + op], ap, h1p[op]);
        }
        float l = boR;
        #pragma unroll
        for (int op = 0; op < 4; op++) {
            float2 h = up2(h1p[op]);
            l = fmaf(woR[2 * op],     fmaxf(h.x, 0.0f), l);
            l = fmaf(woR[2 * op + 1], fmaxf(h.y, 0.0f), l);
        }
        logits[k] = l;
    }

    float mx = logits[0];
    #pragma unroll
    for (int k = 1; k < 9; k++) mx = fmaxf(mx, logits[k]);
    float e[9], ssum = 0.0f;
    #pragma unroll
    for (int k = 0; k < 9; k++) { e[k] = __expf(logits[k] - mx); ssum += e[k]; }
    const float inv = 1.0f / ssum;
    u64 E[9];
    #pragma unroll
    for (int k = 0; k < 9; k++) E[k] = pk2(e[k] * inv, e[k] * inv);

    const u64* X3 = (const u64*)(sm + A3);
    const int hb = iy * HW_ + ix;           // window top-left in halo coords
    float* ob = out + (((size_t)b * 64) << 16) + gy * IMG + gx;
    #pragma unroll 4
    for (int cp = 0; cp < 32; cp++) {
        const u64* xp = X3 + cp * NHP + hb;
        u64 a = 0ull;
        #pragma unroll
        for (int dy = 0; dy < 3; dy++) {
            a = ffma2(E[dy * 3 + 0], xp[dy * HW_ + 0], a);
            a = ffma2(E[dy * 3 + 1], xp[dy * HW_ + 1], a);
            a = ffma2(E[dy * 3 + 2], xp[dy * HW_ + 2], a);
        }
        float2 f = up2(a);
        ob[((size_t)(2 * cp)) << 16]     = f.x;
        ob[((size_t)(2 * cp + 1)) << 16] = f.y;
    }
}

// =============================== launch ====================================
extern "C" void kernel_launch(void* const* d_in, const int* in_sizes, int n_in,
                              void* d_out, int out_size)
{
    const float* x     = (const float*)d_in[0];
    const float* c1w   = (const float*)d_in[1];
    const float* c1b   = (const float*)d_in[2];
    const float* c2w   = (const float*)d_in[3];
    const float* c2b   = (const float*)d_in[4];
    const float* c3w   = (const float*)d_in[5];
    const float* c3b   = (const float*)d_in[6];
    const float* cpw   = (const float*)d_in[7];
    // d_in[8] = convp_b (cancels in position differences)
    const float* bn1g  = (const float*)d_in[9];
    const float* bn1b  = (const float*)d_in[10];
    const float* bn1m  = (const float*)d_in[11];
    const float* bn1v  = (const float*)d_in[12];
    const float* wmid  = (const float*)d_in[13];
    const float* bn2g  = (const float*)d_in[14];
    const float* bn2b  = (const float*)d_in[15];
    const float* bn2m  = (const float*)d_in[16];
    const float* bn2v  = (const float*)d_in[17];
    const float* wout  = (const float*)d_in[18];
    const float* bout  = (const float*)d_in[19];
    float* out = (float*)d_out;

    const int n = in_sizes[0] / (64 * PLANE);   // 16

    cudaFuncSetAttribute(san_conv_kernel,
                         cudaFuncAttributeMaxDynamicSharedMemorySize, K1_SMEMB);
    cudaFuncSetAttribute(san_attn_kernel,
                         cudaFuncAttributeMaxDynamicSharedMemorySize, K2_SMEMB);

    dim3 g1(PLANE / K1_PX, n);                  // (512, 16)
    san_conv_kernel<<<g1, K1_THREADS, K1_SMEMB>>>(x, c1w, c1b, c2w, c2b, c3w, c3b);

    dim3 g2(IMG / TILE_W, IMG / TILE_H, n);     // (8, 32, 16)
    san_attn_kernel<<<g2, K2_THREADS, K2_SMEMB>>>(
        cpw, bn1g, bn1b, bn1m, bn1v, wmid,
        bn2g, bn2b, bn2m, bn2v, wout, bout, out);
}

// round 17
// speedup vs baseline: 1.0100x; 1.0100x over previous
#include <cuda_runtime.h>

// ---------------------------------------------------------------------------
// Fused SAN (pairwise) block, fp32 + packed f32x2 FMA (FFMA2), sm_103a.
// Two-kernel split:
//   K1: 80-ch 1x1 conv GEMM over all pixels -> global scratch (x1,x2,x3)
//   K2: per-tile halo staging from scratch + MLP + softmax + aggregation
// ---------------------------------------------------------------------------

#define IMG   256
#define PLANE (IMG*IMG)
#define NB    16

typedef unsigned long long u64;

__device__ float g_scr[NB * 80 * PLANE];   // 335.5 MB static scratch

__device__ __forceinline__ u64 pk2(float x, float y) {
    u64 r; asm("mov.b64 %0, {%1, %2};" : "=l"(r) : "f"(x), "f"(y)); return r;
}
__device__ __forceinline__ float2 up2(u64 v) {
    float2 f; asm("mov.b64 {%0, %1}, %2;" : "=f"(f.x), "=f"(f.y) : "l"(v)); return f;
}
__device__ __forceinline__ u64 ffma2(u64 a, u64 b, u64 c) {
    u64 d; asm("fma.rn.f32x2 %0, %1, %2, %3;" : "=l"(d) : "l"(a), "l"(b), "l"(c)); return d;
}
__device__ __forceinline__ int reflect(int i) {
    if (i < 0) return -i;
    if (i > IMG - 1) return 2 * (IMG - 1) - i;
    return i;
}

// ============================ K1: conv GEMM ================================
// 256 threads, 2 CTAs/SM. Each CTA: 128 pixels x 80 out-channels.
// smem: WD u64[64][80] dup-pairs (40KB) + BD u64[80] + XC[8][128] (4KB)

#define K1_THREADS 256
#define K1_PX      128          // pixels per CTA (64 pairs)
#define K1_WDF     0            // 10240 floats
#define K1_BDF     10240        // 160 floats
#define K1_XCF     10400        // 1024 floats
#define K1_SMEMF   11424
#define K1_SMEMB   (K1_SMEMF*4)

__global__ void __launch_bounds__(K1_THREADS, 2)
san_conv_kernel(const float* __restrict__ x,
                const float* __restrict__ c1w, const float* __restrict__ c1b,
                const float* __restrict__ c2w, const float* __restrict__ c2b,
                const float* __restrict__ c3w, const float* __restrict__ c3b)
{
    extern __shared__ float sm[];
    u64*   WD = (u64*)sm;                 // [64*80]
    u64*   BD = (u64*)(sm + K1_BDF);      // [80]
    float* XC = sm + K1_XCF;              // [8][128]
    const int tid = threadIdx.x;
    const int P0  = blockIdx.x * K1_PX;
    const int b   = blockIdx.y;

    // stage dup-pair weights + biases
    for (int i = tid; i < 64 * 80; i += K1_THREADS) {
        int c = i / 80, o = i - c * 80;
        float w = (o < 8) ? c1w[o * 64 + c] : (o < 16) ? c2w[(o - 8) * 64 + c]
                                                       : c3w[(o - 16) * 64 + c];
        WD[i] = pk2(w, w);
    }
    if (tid < 80) {
        float bb = (tid < 8) ? c1b[tid] : (tid < 16) ? c2b[tid - 8] : c3b[tid - 16];
        BD[tid] = pk2(bb, bb);
    }

    const float* xb = x + (size_t)b * 64 * PLANE + P0;
    const int hi = tid >> 7, px = tid & 127;

    float pf[4];
    #pragma unroll
    for (int k = 0; k < 4; k++)            // chunk 0 in flight
        pf[k] = xb[(size_t)(2 * k + hi) * PLANE + px];

    const int w    = tid >> 5;             // 0..7 = out-channel group
    const int lane = tid & 31;
    const int o0   = w * 10;
    const int pr0  = lane, pr1 = lane + 32;

    u64 acc[2][10];
    const u64* XC64 = (const u64*)XC;

    for (int cc = 0; cc < 8; cc++) {
        __syncthreads();                    // protect XC (and params on iter 0)
        #pragma unroll
        for (int k = 0; k < 4; k++)
            XC[(2 * k + hi) * 128 + px] = pf[k];
        __syncthreads();

        if (cc == 0) {
            #pragma unroll
            for (int o = 0; o < 10; o++) { acc[0][o] = BD[o0 + o]; acc[1][o] = acc[0][o]; }
        }
        if (cc < 7) {
            const float* src = xb + (size_t)(cc + 1) * 8 * PLANE;
            #pragma unroll
            for (int k = 0; k < 4; k++)
                pf[k] = src[(size_t)(2 * k + hi) * PLANE + px];
        }

        #pragma unroll
        for (int cl = 0; cl < 8; cl++) {
            const int c = cc * 8 + cl;
            const ulonglong2* wp = (const ulonglong2*)(WD + c * 80 + o0);
            ulonglong2 w01 = wp[0], w23 = wp[1], w45 = wp[2], w67 = wp[3], w89 = wp[4];
            u64 X0 = XC64[cl * 64 + pr0];
            u64 X1 = XC64[cl * 64 + pr1];
            acc[0][0] = ffma2(w01.x, X0, acc[0][0]); acc[1][0] = ffma2(w01.x, X1, acc[1][0]);
            acc[0][1] = ffma2(w01.y, X0, acc[0][1]); acc[1][1] = ffma2(w01.y, X1, acc[1][1]);
            acc[0][2] = ffma2(w23.x, X0, acc[0][2]); acc[1][2] = ffma2(w23.x, X1, acc[1][2]);
            acc[0][3] = ffma2(w23.y, X0, acc[0][3]); acc[1][3] = ffma2(w23.y, X1, acc[1][3]);
            acc[0][4] = ffma2(w45.x, X0, acc[0][4]); acc[1][4] = ffma2(w45.x, X1, acc[1][4]);
            acc[0][5] = ffma2(w45.y, X0, acc[0][5]); acc[1][5] = ffma2(w45.y, X1, acc[1][5]);
            acc[0][6] = ffma2(w67.x, X0, acc[0][6]); acc[1][6] = ffma2(w67.x, X1, acc[1][6]);
            acc[0][7] = ffma2(w67.y, X0, acc[0][7]); acc[1][7] = ffma2(w67.y, X1, acc[1][7]);
            acc[0][8] = ffma2(w89.x, X0, acc[0][8]); acc[1][8] = ffma2(w89.x, X1, acc[1][8]);
            acc[0][9] = ffma2(w89.y, X0, acc[0][9]); acc[1][9] = ffma2(w89.y, X1, acc[1][9]);
        }
    }

    float* scr = g_scr + (((size_t)b * 80 + o0) << 16) + P0;
    #pragma unroll
    for (int o = 0; o < 10; o++) {
        *(u64*)(scr + ((size_t)o << 16) + 2 * pr0) = acc[0][o];
        *(u64*)(scr + ((size_t)o << 16) + 2 * pr1) = acc[1][o];
    }
}

// ====================== K2: MLP + softmax + aggregation ====================
// 256 threads (1 thread = 1 pixel), 2 CTAs/SM. Tile 32x8, halo 34x10.

#define TILE_W 32
#define TILE_H 8
#define HW_    34
#define NHP    340
#define K2_THREADS 256

// smem float offsets
#define A1   0            // x1 interior [8][256]
#define A2   2048         // x2 halo     [8][340]
#define A3   4768         // x3 halo ch-pairs u64[32][340]  (21760 floats)
#define GX   26528        // gather idx  int[340]
#define T1o  26868        // folded bn1 shift [10]
#define WOo  26878        // folded w_out [8]
#define PWo  26886        // convp_w [4]
#define BOo  26890        // b_out [1]
#define T2o  26892        // folded bn2 shift pairs u64[4]
#define WMo  26900        // folded w_mid pairs u64[10][4]
#define K2_SMEMF 26980
#define K2_SMEMB (K2_SMEMF*4)   // 107,920 B

__global__ void __launch_bounds__(K2_THREADS, 2)
san_attn_kernel(const float* __restrict__ cpw,
                const float* __restrict__ bn1g, const float* __restrict__ bn1b,
                const float* __restrict__ bn1m, const float* __restrict__ bn1v,
                const float* __restrict__ wmid,
                const float* __restrict__ bn2g, const float* __restrict__ bn2b,
                const float* __restrict__ bn2m, const float* __restrict__ bn2v,
                const float* __restrict__ wout, const float* __restrict__ bout,
                float* __restrict__ out)
{
    extern __shared__ float sm[];
    const int tid = threadIdx.x;
    const int tx0 = blockIdx.x * TILE_W;
    const int ty0 = blockIdx.y * TILE_H;
    const int b   = blockIdx.z;

    // ---- params + gather table ----
    if (tid < 10) {
        float s1 = bn1g[tid] * rsqrtf(bn1v[tid] + 1e-5f);
        sm[T1o + tid] = (bn1b[tid] - bn1m[tid] * s1) / s1;
    }
    if (tid >= 32 && tid < 72) {            // w_mid o-pairs, pre-scaled by s1
        int i = tid - 32, c = i >> 2, op = i & 3;
        float s1c = bn1g[c] * rsqrtf(bn1v[c] + 1e-5f);
        ((u64*)(sm + WMo))[i] =
            pk2(wmid[(2 * op) * 10 + c] * s1c, wmid[(2 * op + 1) * 10 + c] * s1c);
    }
    if (tid >= 96 && tid < 100) {           // bn2 shift pairs
        int op = tid - 96;
        float tv[2];
        #pragma unroll
        for (int j = 0; j < 2; j++) {
            int o = 2 * op + j;
            float s2 = bn2g[o] * rsqrtf(bn2v[o] + 1e-5f);
            tv[j] = (bn2b[o] - bn2m[o] * s2) / s2;
        }
        ((u64*)(sm + T2o))[op] = pk2(tv[0], tv[1]);
    }
    if (tid >= 128 && tid < 136) {
        int o = tid - 128;
        float s2 = bn2g[o] * rsqrtf(bn2v[o] + 1e-5f);
        sm[WOo + o] = wout[o] * s2;
    }
    if (tid >= 160 && tid < 164) sm[PWo + tid - 160] = cpw[tid - 160];
    if (tid == 192) sm[BOo] = bout[0];
    for (int j = tid; j < NHP; j += K2_THREADS) {
        int hy = j / HW_, hx = j - hy * HW_;
        ((int*)sm)[GX + j] = reflect(ty0 - 1 + hy) * IMG + reflect(tx0 - 1 + hx);
    }
    __syncthreads();

    // ---- stage tiles from scratch ----
    const float* sb = g_scr + ((size_t)b * 80 << 16);
    const int* gix = (const int*)sm + GX;
    const int g1 = gix[tid];
    const int g2 = (tid < NHP - K2_THREADS) ? gix[tid + K2_THREADS] : 0;

    {   // x1 interior
        const int iy = tid >> 5, ix = tid & 31;
        const int gp = (ty0 + iy) * IMG + tx0 + ix;
        #pragma unroll
        for (int c = 0; c < 8; c++)
            sm[A1 + c * 256 + tid] = sb[((size_t)c << 16) + gp];
    }
    #pragma unroll
    for (int c = 0; c < 8; c++) {           // x2 halo
        const float* s2p = sb + ((size_t)(8 + c) << 16);
        float v0 = s2p[g1];
        float v1 = (tid < NHP - K2_THREADS) ? s2p[g2] : 0.0f;
        sm[A2 + c * NHP + tid] = v0;
        if (tid < NHP - K2_THREADS) sm[A2 + c * NHP + tid + K2_THREADS] = v1;
    }
    #pragma unroll 4
    for (int ch = 0; ch < 64; ch += 4) {    // x3 halo, channel-pair interleaved
        float v0[4], v1[4];
        #pragma unroll
        for (int q = 0; q < 4; q++) {
            const float* s3 = sb + ((size_t)(16 + ch + q) << 16);
            v0[q] = s3[g1];
            v1[q] = (tid < NHP - K2_THREADS) ? s3[g2] : 0.0f;
        }
        #pragma unroll
        for (int q = 0; q < 4; q++) {
            int cp = (ch + q) >> 1, lo = (ch + q) & 1;
            sm[A3 + (cp * NHP + tid) * 2 + lo] = v0[q];
            if (tid < NHP - K2_THREADS)
                sm[A3 + (cp * NHP + tid + K2_THREADS) * 2 + lo] = v1[q];
        }
    }
    __syncthreads();

    // ---- MLP -> softmax -> aggregation (1 thread = 1 pixel) ----
    const int iy = tid >> 5, ix = tid & 31;
    const int gx = tx0 + ix, gy = ty0 + iy;
    const int hs = (iy + 1) * HW_ + ix + 1;
    const float STEP = 2.0f / 255.0f;
    const float pw00 = sm[PWo], pw01 = sm[PWo + 1], pw10 = sm[PWo + 2], pw11 = sm[PWo + 3];
    const float t18 = sm[T1o + 8], t19 = sm[T1o + 9];
    const float boR = sm[BOo];

    float x1t[8];
    #pragma unroll
    for (int c = 0; c < 8; c++) x1t[c] = sm[A1 + c * 256 + tid] + sm[T1o + c];

    u64 t2p[4], wm8[4], wm9[4];
    #pragma unroll
    for (int op = 0; op < 4; op++) {
        t2p[op] = ((const u64*)(sm + T2o))[op];
        wm8[op] = ((const u64*)(sm + WMo))[8 * 4 + op];
        wm9[op] = ((const u64*)(sm + WMo))[9 * 4 + op];
    }
    float woR[8];
    #pragma unroll
    for (int o = 0; o < 8; o++) woR[o] = sm[WOo + o];

    float logits[9];
    #pragma unroll
    for (int k = 0; k < 9; k++) {
        const int dy = k / 3 - 1, dx = k - (k / 3) * 3 - 1;
        const int hn = hs + dy * HW_ + dx;
        float dlw = (float)(gx - reflect(gx + dx)) * STEP;
        float dlh = (float)(gy - reflect(gy + dy)) * STEP;
        float a8 = fmaxf(pw00 * dlw + pw01 * dlh + t18, 0.0f);
        float a9 = fmaxf(pw10 * dlw + pw11 * dlh + t19, 0.0f);
        u64 a8p = pk2(a8, a8), a9p = pk2(a9, a9);
        u64 h1p[4];
        #pragma unroll
        for (int op = 0; op < 4; op++)
            h1p[op] = ffma2(wm8[op], a8p, ffma2(wm9[op], a9p, t2p[op]));
        #pragma unroll
        for (int c = 0; c < 8; c++) {
            float a = fmaxf(x1t[c] - sm[A2 + c * NHP + hn], 0.0f);
            u64 ap = pk2(a, a);
            #pragma unroll
            for (int op = 0; op < 4; op++)
                h1p[op] = ffma2(((const u64*)(sm + WMo))[c * 4 + op], ap, h1p[op]);
        }
        float l = boR;
        #pragma unroll
        for (int op = 0; op < 4; op++) {
            float2 h = up2(h1p[op]);
            l = fmaf(woR[2 * op],     fmaxf(h.x, 0.0f), l);
            l = fmaf(woR[2 * op + 1], fmaxf(h.y, 0.0f), l);
        }
        logits[k] = l;
    }

    float mx = logits[0];
    #pragma unroll
    for (int k = 1; k < 9; k++) mx = fmaxf(mx, logits[k]);
    float e[9], ssum = 0.0f;
    #pragma unroll
    for (int k = 0; k < 9; k++) { e[k] = __expf(logits[k] - mx); ssum += e[k]; }
    const float inv = 1.0f / ssum;
    u64 E[9];
    #pragma unroll
    for (int k = 0; k < 9; k++) E[k] = pk2(e[k] * inv, e[k] * inv);

    const u64* X3 = (const u64*)(sm + A3);
    const int hb = iy * HW_ + ix;           // window top-left in halo coords
    float* ob = out + (((size_t)b * 64) << 16) + gy * IMG + gx;
    #pragma unroll 4
    for (int cp = 0; cp < 32; cp++) {
        const u64* xp = X3 + cp * NHP + hb;
        u64 a = 0ull;
        #pragma unroll
        for (int dy = 0; dy < 3; dy++) {
            a = ffma2(E[dy * 3 + 0], xp[dy * HW_ + 0], a);
            a = ffma2(E[dy * 3 + 1], xp[dy * HW_ + 1], a);
            a = ffma2(E[dy * 3 + 2], xp[dy * HW_ + 2], a);
        }
        float2 f = up2(a);
        ob[((size_t)(2 * cp)) << 16]     = f.x;
        ob[((size_t)(2 * cp + 1)) << 16] = f.y;
    }
}

// =============================== launch ====================================
extern "C" void kernel_launch(void* const* d_in, const int* in_sizes, int n_in,
                              void* d_out, int out_size)
{
    const float* x     = (const float*)d_in[0];
    const float* c1w   = (const float*)d_in[1];
    const float* c1b   = (const float*)d_in[2];
    const float* c2w   = (const float*)d_in[3];
    const float* c2b   = (const float*)d_in[4];
    const float* c3w   = (const float*)d_in[5];
    const float* c3b   = (const float*)d_in[6];
    const float* cpw   = (const float*)d_in[7];
    // d_in[8] = convp_b (cancels in position differences)
    const float* bn1g  = (const float*)d_in[9];
    const float* bn1b  = (const float*)d_in[10];
    const float* bn1m  = (const float*)d_in[11];
    const float* bn1v  = (const float*)d_in[12];
    const float* wmid  = (const float*)d_in[13];
    const float* bn2g  = (const float*)d_in[14];
    const float* bn2b  = (const float*)d_in[15];
    const float* bn2m  = (const float*)d_in[16];
    const float* bn2v  = (const float*)d_in[17];
    const float* wout  = (const float*)d_in[18];
    const float* bout  = (const float*)d_in[19];
    float* out = (float*)d_out;

    const int n = in_sizes[0] / (64 * PLANE);   // 16

    cudaFuncSetAttribute(san_conv_kernel,
                         cudaFuncAttributeMaxDynamicSharedMemorySize, K1_SMEMB);
    cudaFuncSetAttribute(san_attn_kernel,
                         cudaFuncAttributeMaxDynamicSharedMemorySize, K2_SMEMB);

    dim3 g1(PLANE / K1_PX, n);                  // (512, 16)
    san_conv_kernel<<<g1, K1_THREADS, K1_SMEMB>>>(x, c1w, c1b, c2w, c2b, c3w, c3b);

    dim3 g2(IMG / TILE_W, IMG / TILE_H, n);     // (8, 32, 16)
    san_attn_kernel<<<g2, K2_THREADS, K2_SMEMB>>>(
        cpw, bn1g, bn1b, bn1m, bn1v, wmid,
        bn2g, bn2b, bn2m, bn2v, wout, bout, out);
}